// round 7
// baseline (speedup 1.0000x reference)
#include <cuda_runtime.h>
#include <cstdint>

// DepConv3D R7: 4px x 4oc per thread (32 acc regs) so 3 CTAs/SM = 24 warps
// (R6 was register-bound at 16 warps, fma pipe only 56% busy). Each CTA
// covers 16 of the 32 output channels (oc-half in blockIdx.z). Same f32x2
// slice-pair math + AND gating as R6.

#define BB 4
#define CC 16
#define HH 512
#define WW 512
#define OCC 32
#define TW 64
#define TH 4
#define FT_ROWS 6
#define SPAIRS 70                       // pair-columns; gx = x0 + s - 5
#define SW_ENT (9*16*8)                 // float4 entries per CTA (16 oc)
#define SW_BYTES (SW_ENT*16)            // 18432
#define SF_BYTES (CC*FT_ROWS*SPAIRS*8)  // 53760
#define SD_BYTES (FT_ROWS*SPAIRS*4)     // 1680
#define SMEM_TOTAL (SW_BYTES + SF_BYTES + SD_BYTES)   // 73872

__device__ float4 g_wpack[9 * 16 * 16];

__global__ void pack_weights_kernel(const float* __restrict__ wgt)
{
    int idx = blockIdx.x * blockDim.x + threadIdx.x;   // (k*16+i)*16+g
    if (idx < 9 * 16 * 16) {
        int g = idx & 15;
        int i = (idx >> 4) & 15;
        int k = idx >> 8;
        int oc0 = 2 * g, oc1 = 2 * g + 1;
        float4 v;
        v.x = wgt[((oc0 * CC + i) * 3 + 0) * 9 + k];   // W0[oc0]
        v.y = wgt[((oc0 * CC + i) * 3 + 1) * 9 + k];   // W1[oc0]
        v.z = wgt[((oc1 * CC + i) * 3 + 0) * 9 + k];   // W0[oc1]
        v.w = wgt[((oc1 * CC + i) * 3 + 1) * 9 + k];   // W1[oc1]
        g_wpack[idx] = v;
    }
}

__global__ __launch_bounds__(256, 3)
void depconv3d_kernel(const float* __restrict__ feat,
                      const int*   __restrict__ depth,
                      float* __restrict__ out)
{
    extern __shared__ char smem[];
    float4* sW = (float4*)smem;                        // [k][i][gl] gl=0..7
    float2* sF = (float2*)(smem + SW_BYTES);           // [i][r][s] dup (f,f)
    int*    sD = (int*)(smem + SW_BYTES + SF_BYTES);   // [r][s]

    const int tx = threadIdx.x;        // 0..15 -> px base x0 + 4*tx
    const int ty = threadIdx.y;        // 0..3  -> row y0 + ty
    const int tz = threadIdx.z;        // 0..3  -> 4 oc: ohalf*16 + 4*tz + 0..3
    const int tid = tx + 16 * ty + 64 * tz;
    const int bz = blockIdx.z;
    const int b     = bz >> 1;
    const int ohalf = bz & 1;
    const int y0 = blockIdx.y * TH;
    const int x0 = blockIdx.x * TW;

    // ---- stage this half's packed weights ----
    for (int idx = tid; idx < SW_ENT; idx += 256)
        sW[idx] = g_wpack[((idx >> 3) << 4) + ohalf * 8 + (idx & 7)];

    // ---- depth tile: s <-> gx = x0 + s - 5 ----
    for (int idx = tid; idx < FT_ROWS * SPAIRS; idx += 256) {
        int r = idx / SPAIRS, s = idx - r * SPAIRS;
        int gy = y0 + r - 1, gx = x0 + s - 5;
        int d = 0;
        if (gy >= 0 && gy < HH && gx >= 0 && gx < WW)
            d = depth[(b * HH + gy) * WW + gx];
        sD[idx] = d;
    }

    // ---- feature tiles, duplicated (f,f) ----
    for (int idx = tid; idx < CC * FT_ROWS * SPAIRS; idx += 256) {
        int s   = idx % SPAIRS;
        int rem = idx / SPAIRS;
        int r   = rem % FT_ROWS;
        int i   = rem / FT_ROWS;
        int gy = y0 + r - 1, gx = x0 + s - 5;
        float v = 0.f;
        if (gy >= 0 && gy < HH && gx >= 0 && gx < WW)
            v = feat[((size_t)(b * CC + i) * HH + gy) * WW + gx];
        sF[idx] = make_float2(v, v);
    }
    __syncthreads();

    // ---- per-pixel 9-bit masks (A: dn==dc-1, B: dn==dc) ----
    unsigned mA[4], mB[4];
    #pragma unroll
    for (int p = 0; p < 4; p++) {
        int dc = sD[(ty + 1) * SPAIRS + 4 * tx + p + 5];
        unsigned a = 0, bm = 0;
        #pragma unroll
        for (int k = 0; k < 9; k++) {
            int ky = k / 3, kx = k - ky * 3;
            int dn = sD[(ty + ky) * SPAIRS + 4 * tx + p + kx + 4];
            a  |= (unsigned)(dn == dc - 1) << k;
            bm |= (unsigned)(dn == dc)     << k;
        }
        mA[p] = a; mB[p] = bm;
    }

    unsigned long long acc[4][4];
    #pragma unroll
    for (int p = 0; p < 4; p++)
        #pragma unroll
        for (int o = 0; o < 4; o++) acc[p][o] = 0ull;

    const unsigned fw = (unsigned)__cvta_generic_to_shared(sF);
    const unsigned ww = (unsigned)__cvta_generic_to_shared(sW) + (unsigned)(2 * tz) * 16u;

    #pragma unroll 1
    for (int ky = 0; ky < 3; ky++) {
        // gate masks for this ky: (sliceA, sliceB) as -1/0 words
        unsigned long long M[3][4];
        #pragma unroll
        for (int kx = 0; kx < 3; kx++)
            #pragma unroll
            for (int p = 0; p < 4; p++) {
                int k = ky * 3 + kx;
                unsigned lo = ((mA[p] >> k) & 1u) ? 0xFFFFFFFFu : 0u;
                unsigned hi = ((mB[p] >> k) & 1u) ? 0xFFFFFFFFu : 0u;
                M[kx][p] = ((unsigned long long)hi << 32) | lo;
            }

        const unsigned frow = fw + (unsigned)(((ty + ky) * SPAIRS + 4 * tx + 4) * 8);
        const unsigned wk0  = ww + (unsigned)(ky * 3 * 16 * 8) * 16u;

        #pragma unroll 2
        for (int i = 0; i < CC; i++) {
            unsigned fa = frow + (unsigned)(i * FT_ROWS * SPAIRS * 8);
            unsigned long long P[6];
            asm("ld.shared.v2.b64 {%0,%1},[%2];" : "=l"(P[0]), "=l"(P[1]) : "r"(fa));
            asm("ld.shared.v2.b64 {%0,%1},[%2];" : "=l"(P[2]), "=l"(P[3]) : "r"(fa + 16));
            asm("ld.shared.v2.b64 {%0,%1},[%2];" : "=l"(P[4]), "=l"(P[5]) : "r"(fa + 32));

            #pragma unroll
            for (int kx = 0; kx < 3; kx++) {
                unsigned long long G0 = P[kx]     & M[kx][0];
                unsigned long long G1 = P[kx + 1] & M[kx][1];
                unsigned long long G2 = P[kx + 2] & M[kx][2];
                unsigned long long G3 = P[kx + 3] & M[kx][3];
                unsigned wa = wk0 + (unsigned)(((ky * 3 + kx) * 16 + i) * 8 - ky * 3 * 16 * 8) * 16u;
                #pragma unroll
                for (int j = 0; j < 2; j++) {
                    unsigned long long u, v;
                    asm("ld.shared.v2.b64 {%0,%1},[%2];"
                        : "=l"(u), "=l"(v) : "r"(wa + j * 16));   // gl = 2*tz + j
                    asm("fma.rn.f32x2 %0,%1,%2,%0;" : "+l"(acc[0][2*j])   : "l"(G0), "l"(u));
                    asm("fma.rn.f32x2 %0,%1,%2,%0;" : "+l"(acc[0][2*j+1]) : "l"(G0), "l"(v));
                    asm("fma.rn.f32x2 %0,%1,%2,%0;" : "+l"(acc[1][2*j])   : "l"(G1), "l"(u));
                    asm("fma.rn.f32x2 %0,%1,%2,%0;" : "+l"(acc[1][2*j+1]) : "l"(G1), "l"(v));
                    asm("fma.rn.f32x2 %0,%1,%2,%0;" : "+l"(acc[2][2*j])   : "l"(G2), "l"(u));
                    asm("fma.rn.f32x2 %0,%1,%2,%0;" : "+l"(acc[2][2*j+1]) : "l"(G2), "l"(v));
                    asm("fma.rn.f32x2 %0,%1,%2,%0;" : "+l"(acc[3][2*j])   : "l"(G3), "l"(u));
                    asm("fma.rn.f32x2 %0,%1,%2,%0;" : "+l"(acc[3][2*j+1]) : "l"(G3), "l"(v));
                }
            }
        }
    }

    // ---- epilogue: sum slice halves, STG.128 of 4 px per oc ----
    const int gx = x0 + 4 * tx;
    const int gy = y0 + ty;
    #pragma unroll
    for (int o = 0; o < 4; o++) {
        int oc = ohalf * 16 + 4 * tz + o;
        float4 st;
        float2 a0 = *reinterpret_cast<float2*>(&acc[0][o]);
        float2 a1 = *reinterpret_cast<float2*>(&acc[1][o]);
        float2 a2 = *reinterpret_cast<float2*>(&acc[2][o]);
        float2 a3 = *reinterpret_cast<float2*>(&acc[3][o]);
        st.x = a0.x + a0.y; st.y = a1.x + a1.y;
        st.z = a2.x + a2.y; st.w = a3.x + a3.y;
        size_t off = (((size_t)(b * OCC + oc) * HH + gy) * WW) + gx;
        *reinterpret_cast<float4*>(out + off) = st;
    }
}

extern "C" void kernel_launch(void* const* d_in, const int* in_sizes, int n_in,
                              void* d_out, int out_size)
{
    const float* feat  = (const float*)d_in[0];
    const int*   depth = (const int*)d_in[1];
    const float* wgt   = (const float*)d_in[2];
    float* out = (float*)d_out;

    cudaFuncSetAttribute(depconv3d_kernel,
                         cudaFuncAttributeMaxDynamicSharedMemorySize, SMEM_TOTAL);

    pack_weights_kernel<<<(9 * 16 * 16 + 255) / 256, 256>>>(wgt);

    dim3 block(16, 4, 4);
    dim3 grid(WW / TW, HH / TH, BB * 2);   // z = b*2 + ohalf
    depconv3d_kernel<<<grid, block, SMEM_TOTAL>>>(feat, depth, out);
}